// round 1
// baseline (speedup 1.0000x reference)
#include <cuda_runtime.h>
#include <math.h>

#define E    4096
#define H    32
#define D    128
#define PAST 8191
#define KTOT 8192
#define NCHUNK 128
#define CHUNK  64
#define GEMV_ROWS 256   // rows per block segment
#define GEMV_COLS 512   // columns per block (128 threads * float4)

// ---- device scratch (no allocations allowed) ----
__device__ float g_q[E];              // query (biased) after GEMV
__device__ float g_kv[2 * D];         // [key_new | value_new]
__device__ float g_m[NCHUNK * H];     // per-chunk per-head running max
__device__ float g_l[NCHUNK * H];     // per-chunk per-head exp sum
__device__ float g_po[(size_t)NCHUNK * H * D]; // per-chunk unnormalized output
__device__ float g_attn[E];           // merged attention output (h*D + d)

// ---------------------------------------------------------------------------
// init: seed accumulators with biases
// ---------------------------------------------------------------------------
__global__ void init_kernel(const float* __restrict__ qb,
                            const float* __restrict__ kvb) {
    int t = blockIdx.x * blockDim.x + threadIdx.x;
    if (t < E) g_q[t] = qb[t];
    if (t < 2 * D) g_kv[t] = kvb[t];
}

// ---------------------------------------------------------------------------
// GEMV: out[j] += sum_i x[i] * W[i*ncols + j]   (row-major W, streamed rows)
// grid.x = ceil(ncols/512), grid.y = rows/256, 128 threads
// ---------------------------------------------------------------------------
__global__ void gemv_atomic(const float* __restrict__ x,
                            const float* __restrict__ W,
                            float* __restrict__ out,
                            int ncols) {
    __shared__ float xs[GEMV_ROWS];
    const int i0 = blockIdx.y * GEMV_ROWS;
    for (int i = threadIdx.x; i < GEMV_ROWS; i += blockDim.x) xs[i] = x[i0 + i];
    __syncthreads();

    int j = blockIdx.x * GEMV_COLS + threadIdx.x * 4;
    if (j >= ncols) return;

    const float* wp = W + (size_t)i0 * ncols + j;
    float a0 = 0.f, a1 = 0.f, a2 = 0.f, a3 = 0.f;
#pragma unroll 8
    for (int i = 0; i < GEMV_ROWS; i++) {
        float4 w = *(const float4*)wp;
        float xv = xs[i];
        a0 += xv * w.x; a1 += xv * w.y; a2 += xv * w.z; a3 += xv * w.w;
        wp += ncols;
    }
    atomicAdd(&out[j + 0], a0);
    atomicAdd(&out[j + 1], a1);
    atomicAdd(&out[j + 2], a2);
    atomicAdd(&out[j + 3], a3);
}

// ---------------------------------------------------------------------------
// Split-K attention partial: one block per 64-key chunk, 64 threads.
// Thread t owns key k = chunk*64 + t, computes scores for all 32 heads,
// local softmax per head, then weighted-V partial for the chunk.
// ---------------------------------------------------------------------------
__global__ void attn_partial(const float* __restrict__ pk,   // (D, PAST) d-major
                             const float* __restrict__ pv,   // (PAST, D) k-major
                             const float* __restrict__ mask) // (KTOT)
{
    __shared__ float qs[E];            // scaled q, h*D + d
    __shared__ float ss[H * CHUNK];    // scores then exp-weights, h*CHUNK + k
    const int t = threadIdx.x;
    const float scale = 0.088388347648318447f; // 1/sqrt(128)

    for (int i = t; i < E; i += CHUNK) qs[i] = g_q[i] * scale;
    __syncthreads();

    const int kbase = blockIdx.x * CHUNK;
    const int k = kbase + t;

    // key source: past_key is d-major (stride PAST along d); new key in g_kv
    const float* kp;
    int kstride;
    if (k < PAST) { kp = pk + k; kstride = PAST; }
    else          { kp = g_kv;  kstride = 1;    }

    float acc[H];
#pragma unroll
    for (int h = 0; h < H; h++) acc[h] = 0.f;

#pragma unroll 1
    for (int d4 = 0; d4 < D / 4; d4++) {
        float k0 = kp[0];
        float k1 = kp[kstride];
        float k2 = kp[2 * kstride];
        float k3 = kp[3 * kstride];
        kp += 4 * kstride;
#pragma unroll
        for (int h = 0; h < H; h++) {
            float4 qv = *(const float4*)&qs[h * D + d4 * 4];
            acc[h] += qv.x * k0 + qv.y * k1 + qv.z * k2 + qv.w * k3;
        }
    }

    float mk = mask[k];
#pragma unroll
    for (int h = 0; h < H; h++) ss[h * CHUNK + t] = acc[h] + mk;
    __syncthreads();

    // per-head local softmax stats (threads 0..31, head = t)
    if (t < H) {
        const int h = t;
        float m = -1e30f;
        for (int j = 0; j < CHUNK; j++) m = fmaxf(m, ss[h * CHUNK + j]);
        float l = 0.f;
        for (int j = 0; j < CHUNK; j++) {
            float e = __expf(ss[h * CHUNK + j] - m);
            ss[h * CHUNK + j] = e;
            l += e;
        }
        g_m[blockIdx.x * H + h] = m;
        g_l[blockIdx.x * H + h] = l;
    }
    __syncthreads();

    // weighted V partial: two passes over d (thread t -> d = pass*64 + t)
#pragma unroll 1
    for (int pass = 0; pass < 2; pass++) {
        const int d = pass * 64 + t;
        float o[H];
#pragma unroll
        for (int h = 0; h < H; h++) o[h] = 0.f;

#pragma unroll 1
        for (int j4 = 0; j4 < CHUNK / 4; j4++) {
            const int j = j4 * 4;
            const int kk = kbase + j;
            float v0 = (kk + 0 < PAST) ? pv[(size_t)(kk + 0) * D + d] : g_kv[D + d];
            float v1 = (kk + 1 < PAST) ? pv[(size_t)(kk + 1) * D + d] : g_kv[D + d];
            float v2 = (kk + 2 < PAST) ? pv[(size_t)(kk + 2) * D + d] : g_kv[D + d];
            float v3 = (kk + 3 < PAST) ? pv[(size_t)(kk + 3) * D + d] : g_kv[D + d];
#pragma unroll
            for (int h = 0; h < H; h++) {
                float4 w = *(const float4*)&ss[h * CHUNK + j];
                o[h] += w.x * v0 + w.y * v1 + w.z * v2 + w.w * v3;
            }
        }
#pragma unroll
        for (int h = 0; h < H; h++)
            g_po[((size_t)blockIdx.x * H + h) * D + d] = o[h];
    }
}

// ---------------------------------------------------------------------------
// Combine partials (blocks 0..31 = heads, 128 threads = d).
// Block 32: initialize d_out with proj bias + write key_perm / value_new tail.
// ---------------------------------------------------------------------------
__global__ void combine_kernel(const float* __restrict__ proj_b,
                               float* __restrict__ out) {
    if (blockIdx.x == H) {
        for (int j = threadIdx.x; j < E; j += blockDim.x) out[j] = proj_b[j];
        if (threadIdx.x < D) {
            out[E + threadIdx.x]     = g_kv[threadIdx.x];       // key_perm
            out[E + D + threadIdx.x] = g_kv[D + threadIdx.x];   // value_new
        }
        return;
    }
    const int h = blockIdx.x;
    const int d = threadIdx.x;

    float m = -1e30f;
    for (int c = 0; c < NCHUNK; c++) m = fmaxf(m, g_m[c * H + h]);

    float L = 0.f, o = 0.f;
    for (int c = 0; c < NCHUNK; c++) {
        float sc = __expf(g_m[c * H + h] - m);
        L += g_l[c * H + h] * sc;
        o += g_po[((size_t)c * H + h) * D + d] * sc;
    }
    g_attn[h * D + d] = o / L;
}

// ---------------------------------------------------------------------------
extern "C" void kernel_launch(void* const* d_in, const int* in_sizes, int n_in,
                              void* d_out, int out_size) {
    const float* hs   = (const float*)d_in[0];
    const float* pk   = (const float*)d_in[1];
    const float* pv   = (const float*)d_in[2];
    const float* mask = (const float*)d_in[3];
    const float* qw   = (const float*)d_in[4];
    const float* qb   = (const float*)d_in[5];
    const float* kvw  = (const float*)d_in[6];
    const float* kvb  = (const float*)d_in[7];
    const float* pw   = (const float*)d_in[8];
    const float* pb   = (const float*)d_in[9];
    float* out = (float*)d_out;

    float *gq = nullptr, *gkv = nullptr, *gattn = nullptr;
    cudaGetSymbolAddress((void**)&gq,    g_q);
    cudaGetSymbolAddress((void**)&gkv,   g_kv);
    cudaGetSymbolAddress((void**)&gattn, g_attn);

    // 1) seed biases
    init_kernel<<<16, 256>>>(qb, kvb);

    // 2) q = h @ q_w + q_b   (grid 8x16 = 128 blocks)
    gemv_atomic<<<dim3(8, 16), 128>>>(hs, qw, gq, E);

    // 3) kv = h @ kv_w + kv_b (grid 1x16)
    gemv_atomic<<<dim3(1, 16), 128>>>(hs, kvw, gkv, 2 * D);

    // 4) split-K attention partials
    attn_partial<<<NCHUNK, CHUNK>>>(pk, pv, mask);

    // 5) merge partials; init output with proj bias; write kv outputs
    combine_kernel<<<H + 1, 128>>>(pb, out);

    // 6) out[0:4096] += attn @ proj_w
    gemv_atomic<<<dim3(8, 16), 128>>>(gattn, pw, out, E);
}

// round 2
// speedup vs baseline: 2.4803x; 2.4803x over previous
#include <cuda_runtime.h>
#include <math.h>

#define E    4096
#define H    32
#define D    128
#define PAST 8191
#define KTOT 8192
#define NCHUNK 128
#define CHUNK  64

// GEMV tiling: 256 threads * float4 = 1024 cols per block, 32 rows per segment
#define GB_COLS 1024
#define GB_ROWS 32

// ---- device scratch (no allocations allowed) ----
__device__ float g_q[E];              // query (biased) after GEMV
__device__ float g_kv[2 * D];         // [key_new | value_new]
__device__ float g_m[NCHUNK * H];     // per-chunk per-head running max
__device__ float g_l[NCHUNK * H];     // per-chunk per-head exp sum
__device__ float g_po[(size_t)NCHUNK * H * D]; // per-chunk unnormalized output
__device__ float g_attn[E];           // merged attention output (h*D + d)

// ---------------------------------------------------------------------------
__global__ void init_kernel(const float* __restrict__ qb,
                            const float* __restrict__ kvb) {
    int t = blockIdx.x * blockDim.x + threadIdx.x;
    if (t < E) g_q[t] = qb[t];
    if (t < 2 * D) g_kv[t] = kvb[t];
}

// ---------------------------------------------------------------------------
// GEMV: out[j] += sum_i x[i] * W[i*ncols + j]
// grid = (ceil(ncols/1024), nrows/32), 256 threads
// ---------------------------------------------------------------------------
__global__ void gemv_atomic(const float* __restrict__ x,
                            const float* __restrict__ W,
                            float* __restrict__ out,
                            int ncols) {
    __shared__ float xs[GB_ROWS];
    const int i0 = blockIdx.y * GB_ROWS;
    if (threadIdx.x < GB_ROWS) xs[threadIdx.x] = x[i0 + threadIdx.x];
    __syncthreads();

    int j = blockIdx.x * GB_COLS + threadIdx.x * 4;
    if (j >= ncols) return;

    const float* wp = W + (size_t)i0 * ncols + j;
    float a0 = 0.f, a1 = 0.f, a2 = 0.f, a3 = 0.f;
#pragma unroll 8
    for (int i = 0; i < GB_ROWS; i++) {
        float4 w = __ldg((const float4*)(wp + (size_t)i * ncols));
        float xv = xs[i];
        a0 += xv * w.x; a1 += xv * w.y; a2 += xv * w.z; a3 += xv * w.w;
    }
    atomicAdd(&out[j + 0], a0);
    atomicAdd(&out[j + 1], a1);
    atomicAdd(&out[j + 2], a2);
    atomicAdd(&out[j + 3], a3);
}

// ---------------------------------------------------------------------------
// Split-K attention partial: one block per 64-key chunk, 256 threads.
// Dynamic smem layout:
//   qs  [E]            scaled q (h*D + d)                 16 KB
//   kvs [CHUNK*D]      K tile (d*64+k) then V tile (k*128+d)  32 KB
//   ss  [H*CHUNK]      scores -> exp weights (h*64+k)      8 KB
// ---------------------------------------------------------------------------
__global__ void attn_partial(const float* __restrict__ pk,   // (D, PAST) d-major
                             const float* __restrict__ pv,   // (PAST, D) k-major
                             const float* __restrict__ mask) // (KTOT)
{
    extern __shared__ float smem[];
    float* qs  = smem;                 // E
    float* kvs = smem + E;             // CHUNK*D
    float* ss  = smem + E + CHUNK * D; // H*CHUNK

    const int t = threadIdx.x;
    const int kbase = blockIdx.x * CHUNK;
    const float scale = 0.088388347648318447f; // 1/sqrt(128)

    // load scaled q
    for (int i = t; i < E; i += 256) qs[i] = g_q[i] * scale;

    // load K tile: kvs[d*64 + k] = K[d, kbase+k]
    for (int idx = t; idx < D * CHUNK; idx += 256) {
        int d = idx >> 6;
        int k = idx & 63;
        int kg = kbase + k;
        kvs[idx] = (kg < PAST) ? pk[(size_t)d * PAST + kg] : g_kv[d];
    }
    __syncthreads();

    // ---- score phase: lane k = t&63, warp-group hq = t>>6 owns 8 heads ----
    {
        const int k  = t & 63;
        const int hq = t >> 6;           // 0..3
        float acc[8];
#pragma unroll
        for (int h = 0; h < 8; h++) acc[h] = 0.f;

#pragma unroll 4
        for (int d4 = 0; d4 < D / 4; d4++) {
            const int d = d4 * 4;
            float k0 = kvs[(d + 0) * CHUNK + k];
            float k1 = kvs[(d + 1) * CHUNK + k];
            float k2 = kvs[(d + 2) * CHUNK + k];
            float k3 = kvs[(d + 3) * CHUNK + k];
#pragma unroll
            for (int h = 0; h < 8; h++) {
                float4 qv = *(const float4*)&qs[(hq * 8 + h) * D + d];
                acc[h] += qv.x * k0 + qv.y * k1 + qv.z * k2 + qv.w * k3;
            }
        }
        float mk = mask[kbase + k];
#pragma unroll
        for (int h = 0; h < 8; h++) ss[(hq * 8 + h) * CHUNK + k] = acc[h] + mk;
    }
    __syncthreads();

    // ---- per-head local softmax stats (threads 0..31, head = t) ----
    if (t < H) {
        const int h = t;
        float m = -1e30f;
#pragma unroll 8
        for (int j = 0; j < CHUNK; j++) m = fmaxf(m, ss[h * CHUNK + j]);
        float l = 0.f;
#pragma unroll 8
        for (int j = 0; j < CHUNK; j++) {
            float e = __expf(ss[h * CHUNK + j] - m);
            ss[h * CHUNK + j] = e;
            l += e;
        }
        g_m[blockIdx.x * H + h] = m;
        g_l[blockIdx.x * H + h] = l;
    }
    __syncthreads();

    // ---- load V tile: kvs[k*128 + d] = V[kbase+k, d] ----
    for (int idx = t; idx < CHUNK * D; idx += 256) {
        int k = idx >> 7;
        int d = idx & 127;
        int kg = kbase + k;
        kvs[idx] = (kg < PAST) ? pv[(size_t)kg * D + d] : g_kv[D + d];
    }
    __syncthreads();

    // ---- V phase: d = t&127, half = t>>7 owns 16 heads ----
    {
        const int d  = t & 127;
        const int hh = t >> 7;           // 0..1
        float o[16];
#pragma unroll
        for (int h = 0; h < 16; h++) o[h] = 0.f;

#pragma unroll 2
        for (int j4 = 0; j4 < CHUNK / 4; j4++) {
            const int j = j4 * 4;
            float v0 = kvs[(j + 0) * D + d];
            float v1 = kvs[(j + 1) * D + d];
            float v2 = kvs[(j + 2) * D + d];
            float v3 = kvs[(j + 3) * D + d];
#pragma unroll
            for (int h = 0; h < 16; h++) {
                float4 w = *(const float4*)&ss[(hh * 16 + h) * CHUNK + j];
                o[h] += w.x * v0 + w.y * v1 + w.z * v2 + w.w * v3;
            }
        }
#pragma unroll
        for (int h = 0; h < 16; h++)
            g_po[((size_t)blockIdx.x * H + hh * 16 + h) * D + d] = o[h];
    }
}

// ---------------------------------------------------------------------------
// Combine partials (blocks 0..31 = heads, 128 threads = d).
// Block 32: initialize d_out with proj bias + write key_perm / value_new tail.
// ---------------------------------------------------------------------------
__global__ void combine_kernel(const float* __restrict__ proj_b,
                               float* __restrict__ out) {
    if (blockIdx.x == H) {
        for (int j = threadIdx.x; j < E; j += blockDim.x) out[j] = proj_b[j];
        if (threadIdx.x < D) {
            out[E + threadIdx.x]     = g_kv[threadIdx.x];       // key_perm
            out[E + D + threadIdx.x] = g_kv[D + threadIdx.x];   // value_new
        }
        return;
    }
    const int h = blockIdx.x;
    const int d = threadIdx.x;

    float m = -1e30f;
#pragma unroll 8
    for (int c = 0; c < NCHUNK; c++) m = fmaxf(m, g_m[c * H + h]);

    float L = 0.f, o = 0.f;
#pragma unroll 4
    for (int c = 0; c < NCHUNK; c++) {
        float sc = __expf(g_m[c * H + h] - m);
        L += g_l[c * H + h] * sc;
        o += g_po[((size_t)c * H + h) * D + d] * sc;
    }
    g_attn[h * D + d] = o / L;
}

// ---------------------------------------------------------------------------
extern "C" void kernel_launch(void* const* d_in, const int* in_sizes, int n_in,
                              void* d_out, int out_size) {
    const float* hs   = (const float*)d_in[0];
    const float* pk   = (const float*)d_in[1];
    const float* pv   = (const float*)d_in[2];
    const float* mask = (const float*)d_in[3];
    const float* qw   = (const float*)d_in[4];
    const float* qb   = (const float*)d_in[5];
    const float* kvw  = (const float*)d_in[6];
    const float* kvb  = (const float*)d_in[7];
    const float* pw   = (const float*)d_in[8];
    const float* pb   = (const float*)d_in[9];
    float* out = (float*)d_out;

    float *gq = nullptr, *gkv = nullptr, *gattn = nullptr;
    cudaGetSymbolAddress((void**)&gq,    g_q);
    cudaGetSymbolAddress((void**)&gkv,   g_kv);
    cudaGetSymbolAddress((void**)&gattn, g_attn);

    const int attn_smem = (E + CHUNK * D + H * CHUNK) * (int)sizeof(float); // 56 KB
    static int smem_set = 0;
    if (!smem_set) {
        cudaFuncSetAttribute(attn_partial,
                             cudaFuncAttributeMaxDynamicSharedMemorySize,
                             attn_smem);
        smem_set = 1;
    }

    // 1) seed biases
    init_kernel<<<16, 256>>>(qb, kvb);

    // 2) q = h @ q_w + q_b   (grid 4x128 = 512 blocks)
    gemv_atomic<<<dim3(4, 128), 256>>>(hs, qw, gq, E);

    // 3) kv = h @ kv_w + kv_b (grid 1x128)
    gemv_atomic<<<dim3(1, 128), 256>>>(hs, kvw, gkv, 2 * D);

    // 4) split-K attention partials
    attn_partial<<<NCHUNK, 256, attn_smem>>>(pk, pv, mask);

    // 5) merge partials; init output with proj bias; write kv outputs
    combine_kernel<<<H + 1, 128>>>(pb, out);

    // 6) out[0:4096] += attn @ proj_w
    gemv_atomic<<<dim3(4, 128), 256>>>(gattn, pw, out, E);
}